// round 17
// baseline (speedup 1.0000x reference)
#include <cuda_runtime.h>
#include <cuda_bf16.h>
#include <cstdint>

// VQ lookup via warp-level bf16 mma.sync (HMMA) + candidate-limited exact refine.
// R16 = R15 (198us) with fatter phases:
//   - KC=128 (4 chunks instead of 8): half the exposed-latency windows/barriers
//   - cb tile via cp.async issued BEFORE the z fill: L2 latency hides under it
// Numerics identical to R15: single-pass zh*ch approx, TAU=1.0 top-2 gap,
// candidate-limited exact fp32 refine (codes within TAU of approx min).

#define D_DIM   510
#define K_CODES 128
#define BM      128
#define KC      128          // K-chunk (elements)
#define NCH     4            // 4*128 = 512, cols 510/511 zeroed
#define TAU     1.0f
#define NCAND   8
#define ST      272          // bf16 tile row stride BYTES (136 bf16); 17*16B

// smem byte offsets
#define SM_CSQ  0                        // 128 f32
#define SM_KF   512                      // 128 i32
#define SM_FLG  1024                     // 128 i32
#define SM_BV   1536                     // 2*128 f32
#define SM_SV   2560                     // 2*128 f32
#define SM_BK   3584                     // 2*128 i32
#define SM_CNT  4608                     // 128 i32
#define SM_RBV  5120                     // 128 f32
#define SM_CAND 5632                     // 128*8 i32
#define SM_ZH   9728                     // 128*272 = 34816
#define SM_CH   (SM_ZH + 128*ST)
#define SMEM_BYTES (SM_CH + 128*ST)      // 79360 -> 2 CTAs/SM

__device__ float g_csq[K_CODES];
__device__ __align__(128) __nv_bfloat16 g_cbh[K_CODES * 512];  // 512-padded rows

// ---------------------------------------------------------------- prep: c_sq + cb bf16
__global__ void prep_kernel(const float* __restrict__ cb) {
    int k = blockIdx.x, tid = threadIdx.x;
    float s = 0.f;
    for (int d = tid; d < 512; d += 256) {
        float v = (d < D_DIM) ? cb[k * D_DIM + d] : 0.f;
        g_cbh[k * 512 + d] = __float2bfloat16(v);
        s = fmaf(v, v, s);
    }
    #pragma unroll
    for (int off = 16; off; off >>= 1) s += __shfl_xor_sync(0xffffffffu, s, off);
    __shared__ float red[8];
    if ((tid & 31) == 0) red[tid >> 5] = s;
    __syncthreads();
    if (tid == 0) {
        float t = 0.f;
        #pragma unroll
        for (int i = 0; i < 8; i++) t += red[i];
        g_csq[k] = t;
    }
}

// ---------------------------------------------------------------- helpers
__device__ __forceinline__ uint32_t pack2(__nv_bfloat16 a, __nv_bfloat16 b) {
    return (uint32_t)__bfloat16_as_ushort(b) << 16 | (uint32_t)__bfloat16_as_ushort(a);
}
__device__ __forceinline__ void cp_async16(uint32_t dst, const void* src) {
    asm volatile("cp.async.ca.shared.global [%0], [%1], 16;" :: "r"(dst), "l"(src));
}
__device__ __forceinline__ void cp_commit() {
    asm volatile("cp.async.commit_group;");
}
template <int N>
__device__ __forceinline__ void cp_wait() {
    asm volatile("cp.async.wait_group %0;" :: "n"(N));
}
__device__ __forceinline__ void ldm4(uint32_t* r, uint32_t addr) {
    asm volatile("ldmatrix.sync.aligned.m8n8.x4.shared.b16 {%0,%1,%2,%3}, [%4];"
                 : "=r"(r[0]), "=r"(r[1]), "=r"(r[2]), "=r"(r[3]) : "r"(addr));
}
__device__ __forceinline__ void mma16816(float* d, const uint32_t* a,
                                         const uint32_t* b) {
    asm volatile(
        "mma.sync.aligned.m16n8k16.row.col.f32.bf16.bf16.f32 "
        "{%0,%1,%2,%3}, {%4,%5,%6,%7}, {%8,%9}, {%0,%1,%2,%3};"
        : "+f"(d[0]), "+f"(d[1]), "+f"(d[2]), "+f"(d[3])
        : "r"(a[0]), "r"(a[1]), "r"(a[2]), "r"(a[3]), "r"(b[0]), "r"(b[1]));
}
__device__ __forceinline__ void merge2(float& bv, float& sv, int& bk,
                                       float obv, float osv, int obk) {
    if (obv < bv) { sv = fminf(bv, osv); bv = obv; bk = obk; }
    else          { sv = fminf(sv, obv); }
}

extern __shared__ __align__(128) char smem[];

// ---------------------------------------------------------------- main kernel
__global__ __launch_bounds__(256, 2)
void vq_mma_kernel(const float* __restrict__ z,
                   const float* __restrict__ cb,
                   float* __restrict__ out) {
    const uint32_t sbase = (uint32_t)__cvta_generic_to_shared(smem);
    const int tid  = threadIdx.x;
    const int wid  = tid >> 5;
    const int lane = tid & 31;
    const int wr   = wid & 3;       // row group: 4 x 32 rows
    const int wc   = wid >> 2;      // code group: 2 x 64 codes
    const long long row0 = (long long)blockIdx.x * BM;

    if (tid < K_CODES) *(float*)(smem + SM_CSQ + tid * 4) = g_csq[tid];

    const float* zg = z + row0 * D_DIM;

    float acc[2][8][4];
    #pragma unroll
    for (int mt = 0; mt < 2; ++mt)
        #pragma unroll
        for (int nt = 0; nt < 8; ++nt)
            #pragma unroll
            for (int q = 0; q < 4; ++q) acc[mt][nt][q] = 0.f;

    // ldmatrix lane->address geometry (byte offsets within a tile)
    const uint32_t a_off = (uint32_t)((wr * 32 + (lane & 15)) * ST + ((lane >> 4) * 8) * 2);
    const uint32_t b_off = (uint32_t)((wc * 64 + ((lane >> 4) << 3) + (lane & 7)) * ST
                                      + (((lane >> 3) & 1) * 8) * 2);
    // z load/convert geometry: 32 threads per row, 4 floats each (KC=128)
    const int lr0 = tid >> 5;        // 0..7, +8 per iter (16 iters -> 128 rows)
    const int lkq = (tid & 31) * 4;  // 0,4,...,124

    for (int ch = 0; ch < NCH; ++ch) {
        __syncthreads();             // tiles free (prev chunk's mma done)
        const int gk = ch * KC + lkq;
        const bool tail = (gk == 508);

        // ---- cb tile first: fire-and-forget cp.async (L2-hot, no reg consumer)
        #pragma unroll
        for (int it = 0; it < 8; ++it) {
            const int idx = it * 256 + tid;   // 0..2047
            const int r = idx >> 4;           // code row 0..127
            const int q = idx & 15;           // uint4 slot within 256B
            const char* src = (const char*)g_cbh + r * 1024 + ch * (KC * 2) + q * 16;
            cp_async16(sbase + SM_CH + (uint32_t)(r * ST + q * 16), src);
        }
        cp_commit();

        // ---- z tile: load fp32, round to bf16 (cb latency hides under this)
        #pragma unroll
        for (int it = 0; it < 16; ++it) {
            const int r = lr0 + it * 8;
            const uint32_t so = (uint32_t)(r * ST + lkq * 2);
            const float* p = zg + (long long)r * D_DIM + gk;
            float2 a = *(const float2*)p;
            float2 b = tail ? make_float2(0.f, 0.f) : *(const float2*)(p + 2);
            __nv_bfloat16 h0 = __float2bfloat16(a.x);
            __nv_bfloat16 h1 = __float2bfloat16(a.y);
            __nv_bfloat16 h2 = __float2bfloat16(b.x);
            __nv_bfloat16 h3 = __float2bfloat16(b.y);
            *(uint2*)(smem + SM_ZH + so) = make_uint2(pack2(h0,h1), pack2(h2,h3));
        }
        cp_wait<0>();
        __syncthreads();

        // ---- mma over 8 k-steps of 16: zh x ch (single pass)
        #pragma unroll
        for (int ks = 0; ks < 8; ++ks) {
            const uint32_t kb = (uint32_t)(ks * 32);   // 16 bf16 = 32 bytes
            uint32_t ah[2][4];
            #pragma unroll
            for (int mt = 0; mt < 2; ++mt)
                ldm4(ah[mt], sbase + SM_ZH + a_off + (uint32_t)(mt * 16 * ST) + kb);
            #pragma unroll
            for (int np = 0; np < 4; ++np) {           // n-tile pairs
                const uint32_t bo = b_off + (uint32_t)(np * 16 * ST) + kb;
                uint32_t bh[4];
                ldm4(bh, sbase + SM_CH + bo);
                #pragma unroll
                for (int mt = 0; mt < 2; ++mt) {
                    mma16816(acc[mt][np*2+0], ah[mt], bh + 0);
                    mma16816(acc[mt][np*2+1], ah[mt], bh + 2);
                }
            }
        }
    }

    // ---- epilogue: top-2 per row
    const float* csq_s = (const float*)(smem + SM_CSQ);
    float* bvp = (float*)(smem + SM_BV);
    float* svp = (float*)(smem + SM_SV);
    int*   bkp = (int*)(smem + SM_BK);
    int*   flg = (int*)(smem + SM_FLG);
    int*   cnt = (int*)(smem + SM_CNT);
    float* rbv = (float*)(smem + SM_RBV);
    int*   cand = (int*)(smem + SM_CAND);

    #pragma unroll
    for (int mt = 0; mt < 2; ++mt) {
        #pragma unroll
        for (int rh = 0; rh < 2; ++rh) {
            float bv = 3.4e38f, sv = 3.4e38f;
            int bk = 0;
            #pragma unroll
            for (int nt = 0; nt < 8; ++nt) {
                #pragma unroll
                for (int s = 0; s < 2; ++s) {
                    const int c = wc * 64 + nt * 8 + (lane & 3) * 2 + s;
                    const float d2 = fmaf(-2.f, acc[mt][nt][rh * 2 + s], csq_s[c]);
                    if (d2 < bv) { sv = bv; bv = d2; bk = c; }
                    else if (d2 < sv) sv = d2;
                }
            }
            #pragma unroll
            for (int off = 1; off <= 2; off <<= 1) {
                float obv = __shfl_xor_sync(0xffffffffu, bv, off);
                float osv = __shfl_xor_sync(0xffffffffu, sv, off);
                int   obk = __shfl_xor_sync(0xffffffffu, bk, off);
                merge2(bv, sv, bk, obv, osv, obk);
            }
            if ((lane & 3) == 0) {
                const int r = wr * 32 + mt * 16 + rh * 8 + (lane >> 2);
                bvp[wc * 128 + r] = bv;
                svp[wc * 128 + r] = sv;
                bkp[wc * 128 + r] = bk;
            }
        }
    }
    __syncthreads();

    if (tid < BM) {
        float bv = bvp[tid], sv = svp[tid];
        int bk = bkp[tid];
        merge2(bv, sv, bk, bvp[128 + tid], svp[128 + tid], bkp[128 + tid]);
        *(int*)(smem + SM_KF + tid * 4) = bk;
        flg[tid] = ((sv - bv) < TAU) ? 1 : 0;
        rbv[tid] = bv;
        cnt[tid] = 0;
    }
    __syncthreads();

    // ---- candidate collection for flagged rows (rescan registers)
    #pragma unroll
    for (int mt = 0; mt < 2; ++mt) {
        #pragma unroll
        for (int rh = 0; rh < 2; ++rh) {
            const int r = wr * 32 + mt * 16 + rh * 8 + (lane >> 2);
            if (!flg[r]) continue;
            const float thr = rbv[r] + TAU;
            #pragma unroll
            for (int nt = 0; nt < 8; ++nt) {
                #pragma unroll
                for (int s = 0; s < 2; ++s) {
                    const int c = wc * 64 + nt * 8 + (lane & 3) * 2 + s;
                    const float d2 = fmaf(-2.f, acc[mt][nt][rh * 2 + s], csq_s[c]);
                    if (d2 <= thr) {
                        int slot = atomicAdd(&cnt[r], 1);
                        if (slot < NCAND) cand[r * NCAND + slot] = c;
                    }
                }
            }
        }
    }

    // ---- gather: out[row] = codebook[kfin[row]]  (independent of rescan)
    if (tid < 255) {
        const int dpos = tid * 2;
        float* ob = out + row0 * D_DIM + dpos;
        #pragma unroll 4
        for (int r = 0; r < BM; ++r) {
            int k = *(const int*)(smem + SM_KF + r * 4);
            float2 v = *(const float2*)(cb + k * D_DIM + dpos);
            *(float2*)(ob + (long long)r * D_DIM) = v;
        }
    }
    __syncthreads();

    // ---- exact refine of flagged rows over their candidate sets (~5% rows)
    for (int r = wid; r < BM; r += 8) {
        if (!flg[r]) continue;                      // warp-uniform branch
        const long long row = row0 + r;
        const float* zr = z + row * D_DIM;
        float zreg[16];
        #pragma unroll
        for (int t = 0; t < 16; ++t) {
            int d = lane + t * 32;
            zreg[t] = (d < D_DIM) ? zr[d] : 0.f;
        }
        float bv = 3.4e38f;
        int bk = 1 << 30;
        const int n = cnt[r];
        const int m = (n > NCAND) ? K_CODES : n;    // overflow -> full scan
        for (int j = 0; j < m; ++j) {
            const int c = (n > NCAND) ? j : cand[r * NCAND + j];
            const float* cr = cb + c * D_DIM;
            float s = 0.f;
            #pragma unroll
            for (int t = 0; t < 16; ++t) {
                int d = lane + t * 32;
                float cv = (d < D_DIM) ? cr[d] : 0.f;
                s = fmaf(zreg[t], cv, s);
            }
            #pragma unroll
            for (int off = 16; off; off >>= 1)
                s += __shfl_xor_sync(0xffffffffu, s, off);
            float d2 = fmaf(-2.f, s, csq_s[c]);
            if (d2 < bv || (d2 == bv && c < bk)) { bv = d2; bk = c; }
        }
        for (int d = lane; d < D_DIM; d += 32)
            out[row * D_DIM + d] = cb[bk * D_DIM + d];
    }
}

// ---------------------------------------------------------------- launch
extern "C" void kernel_launch(void* const* d_in, const int* in_sizes, int n_in,
                              void* d_out, int out_size) {
    const float* z  = (const float*)d_in[0];
    const float* cb = (const float*)d_in[1];
    float* out = (float*)d_out;

    cudaFuncSetAttribute(vq_mma_kernel, cudaFuncAttributeMaxDynamicSharedMemorySize,
                         SMEM_BYTES);

    const int n_rows  = in_sizes[0] / D_DIM;   // 131072
    const int nblocks = n_rows / BM;           // 1024

    prep_kernel<<<K_CODES, 256>>>(cb);
    vq_mma_kernel<<<nblocks, 256, SMEM_BYTES>>>(z, cb, out);
}